// round 16
// baseline (speedup 1.0000x reference)
#include <cuda_runtime.h>
#include <cuda_fp16.h>
#include <math.h>
#include <stdint.h>

// Problem constants (fixed by reference setup_inputs)
#define CB 4
#define CL 2048
#define CD 256
#define CH 8
#define CDK 32
#define CF 1024

// ---------------------------------------------------------------------------
// Scratch (device globals: allocation-free per harness rules)
// ---------------------------------------------------------------------------
__device__ __align__(16) __half g_mh[CL * CDK];                  // 128 KB
__device__ __align__(16) __half g_P[(size_t)CL * CL];            // 8 MB : exp(scores)
__device__ __align__(16) float  g_den[CB * CL];                  // 32 KB
__device__ __align__(16) __half g_parth[(size_t)4 * 1024 * 1024];// 8 MB : half partials
__device__ __align__(16) float  g_Hn[(size_t)CB * CL * CD];      // 8 MB
__device__ __align__(16) __half g_Hnh[(size_t)CB * CL * CD];     // 4 MB
__device__ __align__(16) __half g_H1h[(size_t)CB * CL * CF];     // 16 MB
__device__ __align__(16) __half g_xh[(size_t)CB * CL * CD];      // 4 MB : masked x, half
__device__ __align__(16) __half g_W1h[(size_t)CD * CF];          // 512 KB
__device__ __align__(16) __half g_W2h[(size_t)CF * CD];          // 512 KB

__device__ __forceinline__ uint32_t packh2(float lo, float hi) {
    __half2 h = __floats2half2_rn(lo, hi);
    return *(uint32_t*)&h;
}
__device__ __forceinline__ float2 h2f(uint32_t u) {
    return __half22float2(*(__half2*)&u);
}

// ---------------------------------------------------------------------------
// mh[l, d] = half( mean over (b, h) of x[b, l, h*32 + d] ); also zeros g_den
// ---------------------------------------------------------------------------
__global__ void k_mean(const float* __restrict__ x) {
    int idx = blockIdx.x * blockDim.x + threadIdx.x;
    if (idx < CB * CL) g_den[idx] = 0.f;
    if (idx >= CL * CDK) return;
    int l = idx / CDK;
    int d = idx % CDK;
    float s = 0.f;
#pragma unroll
    for (int b = 0; b < CB; b++)
#pragma unroll
        for (int h = 0; h < CH; h++)
            s += x[((size_t)(b * CL) + l) * CD + h * CDK + d];
    g_mh[idx] = __float2half_rn(s * (1.f / 32.f));
}

// ---------------------------------------------------------------------------
// mma / ldmatrix / cp.async helpers
// ---------------------------------------------------------------------------
__device__ __forceinline__ void mma16816(float* d, const uint4& a, const uint2& b) {
    asm volatile(
        "mma.sync.aligned.m16n8k16.row.col.f32.f16.f16.f32 "
        "{%0,%1,%2,%3}, {%4,%5,%6,%7}, {%8,%9}, {%0,%1,%2,%3};"
        : "+f"(d[0]), "+f"(d[1]), "+f"(d[2]), "+f"(d[3])
        : "r"(a.x), "r"(a.y), "r"(a.z), "r"(a.w), "r"(b.x), "r"(b.y));
}
__device__ __forceinline__ void ldsm4(uint4& d, uint32_t a) {
    asm volatile("ldmatrix.sync.aligned.m8n8.x4.shared.b16 {%0,%1,%2,%3}, [%4];"
        : "=r"(d.x), "=r"(d.y), "=r"(d.z), "=r"(d.w) : "r"(a));
}
__device__ __forceinline__ void ldsm4t(uint32_t& r0, uint32_t& r1,
                                       uint32_t& r2, uint32_t& r3, uint32_t a) {
    asm volatile("ldmatrix.sync.aligned.m8n8.x4.trans.shared.b16 {%0,%1,%2,%3}, [%4];"
        : "=r"(r0), "=r"(r1), "=r"(r2), "=r"(r3) : "r"(a));
}
__device__ __forceinline__ void cpasync16(uint32_t s, const void* g) {
    asm volatile("cp.async.cg.shared.global [%0], [%1], 16;" :: "r"(s), "l"(g));
}
#define CP_COMMIT() asm volatile("cp.async.commit_group;" ::: "memory")
#define CP_WAIT1()  asm volatile("cp.async.wait_group 1;" ::: "memory")

// ---------------------------------------------------------------------------
// Merged: blocks [0,256)   -> tensor-core scores tile (128x128) + fused
//                             masked denominators (atomicAdd g_den)
//         blocks [256,1280)-> xh convert (masked x -> half)
//         blocks [1280,1408)-> W1h convert
//         blocks [1408,1536)-> W2h convert
// ---------------------------------------------------------------------------
__global__ void __launch_bounds__(256) k_scores_conv(
    const int* __restrict__ mask, const float* __restrict__ x,
    const float* __restrict__ W1, const float* __restrict__ W2) {
    const int bid = blockIdx.x;
    const int tid = threadIdx.x;

    if (bid >= 256) {
        // ---------------- convert path ----------------
        if (bid < 1280) {
            size_t e = ((size_t)(bid - 256) * 256 + tid) * 8;
            int msk = mask[e >> 8];
            float4 v0 = *(const float4*)&x[e];
            float4 v1 = *(const float4*)&x[e + 4];
            if (!msk) {
                v0 = make_float4(0.f, 0.f, 0.f, 0.f);
                v1 = make_float4(0.f, 0.f, 0.f, 0.f);
            }
            uint4 o;
            o.x = packh2(v0.x, v0.y); o.y = packh2(v0.z, v0.w);
            o.z = packh2(v1.x, v1.y); o.w = packh2(v1.z, v1.w);
            *(uint4*)&g_xh[e] = o;
        } else {
            const float* src = (bid < 1408) ? W1 : W2;
            __half* dst = (bid < 1408) ? g_W1h : g_W2h;
            int lb = (bid < 1408) ? bid - 1280 : bid - 1408;
            size_t e = ((size_t)lb * 256 + tid) * 8;
            float4 v0 = *(const float4*)&src[e];
            float4 v1 = *(const float4*)&src[e + 4];
            uint4 o;
            o.x = packh2(v0.x, v0.y); o.y = packh2(v0.z, v0.w);
            o.z = packh2(v1.x, v1.y); o.w = packh2(v1.z, v1.w);
            *(uint4*)&dst[e] = o;
        }
        return;
    }

    // ---------------- scores path ----------------
    __shared__ __align__(16) __half sA[128 * 40];   // 80B row stride
    __shared__ __align__(16) __half sB[128 * 40];
    __shared__ float mk[CB][128];

    const int lane = tid & 31;
    const int wid = tid >> 5;
    const int wr = wid >> 2;
    const int wc = wid & 3;
    const int i0 = (bid >> 4) * 128;
    const int j0 = (bid & 15) * 128;

#pragma unroll
    for (int u = 0; u < 2; u++) {
        int cid = tid + u * 256;
        int r = cid >> 2, c = cid & 3;
        *(uint4*)&sA[r * 40 + c * 8] = *(const uint4*)&g_mh[(i0 + r) * CDK + c * 8];
        *(uint4*)&sB[r * 40 + c * 8] = *(const uint4*)&g_mh[(j0 + r) * CDK + c * 8];
    }
    {
        int b = tid >> 6, j = (tid & 63) * 2;
        mk[b][j]     = (mask[b * CL + j0 + j] != 0) ? 1.f : 0.f;
        mk[b][j + 1] = (mask[b * CL + j0 + j + 1] != 0) ? 1.f : 0.f;
    }
    __syncthreads();

    uint32_t aS = (uint32_t)__cvta_generic_to_shared(sA);
    uint32_t bS = (uint32_t)__cvta_generic_to_shared(sB);

    const int am8 = (lane & 7) + (((lane >> 3) & 1) << 3);
    const int kq  = lane >> 4;

    float acc[4][4][4];
#pragma unroll
    for (int i = 0; i < 4; i++)
#pragma unroll
        for (int j = 0; j < 4; j++)
#pragma unroll
            for (int q = 0; q < 4; q++) acc[i][j][q] = 0.f;

#pragma unroll
    for (int ks = 0; ks < 2; ks++) {
        uint4 af[4];
#pragma unroll
        for (int i = 0; i < 4; i++) {
            int m = wr * 64 + i * 16 + am8;
            ldsm4(af[i], aS + m * 80 + (ks * 2 + kq) * 16);
        }
        uint2 bf[4];
#pragma unroll
        for (int jj = 0; jj < 2; jj++) {
            int n = wc * 32 + jj * 16 + am8;
            uint4 t;
            ldsm4(t, bS + n * 80 + (ks * 2 + kq) * 16);
            bf[jj * 2]     = make_uint2(t.x, t.z);
            bf[jj * 2 + 1] = make_uint2(t.y, t.w);
        }
#pragma unroll
        for (int i = 0; i < 4; i++)
#pragma unroll
            for (int j = 0; j < 4; j++)
                mma16816(acc[i][j], af[i], bf[j]);
    }

    const float PI = 3.14159265358979323846f;
#pragma unroll
    for (int i = 0; i < 4; i++) {
        int row_lo = i0 + wr * 64 + i * 16 + (lane >> 2);
        int row_hi = row_lo + 8;
        float slo[CB] = {0.f, 0.f, 0.f, 0.f};
        float shi[CB] = {0.f, 0.f, 0.f, 0.f};
#pragma unroll
        for (int j = 0; j < 4; j++) {
            int cl = wc * 32 + j * 8 + (lane & 3) * 2;
            float p0 = __expf(0.5f * (1.f - __cosf(fminf(fmaxf(acc[i][j][0], -PI), PI))));
            float p1 = __expf(0.5f * (1.f - __cosf(fminf(fmaxf(acc[i][j][1], -PI), PI))));
            float p2 = __expf(0.5f * (1.f - __cosf(fminf(fmaxf(acc[i][j][2], -PI), PI))));
            float p3 = __expf(0.5f * (1.f - __cosf(fminf(fmaxf(acc[i][j][3], -PI), PI))));
            uint32_t wlo = packh2(p0, p1);
            uint32_t whi = packh2(p2, p3);
            *(uint32_t*)&g_P[(size_t)row_lo * CL + j0 + cl] = wlo;
            *(uint32_t*)&g_P[(size_t)row_hi * CL + j0 + cl] = whi;
            float2 flo = h2f(wlo);
            float2 fhi = h2f(whi);
#pragma unroll
            for (int b = 0; b < CB; b++) {
                slo[b] += flo.x * mk[b][cl] + flo.y * mk[b][cl + 1];
                shi[b] += fhi.x * mk[b][cl] + fhi.y * mk[b][cl + 1];
            }
        }
#pragma unroll
        for (int b = 0; b < CB; b++) {
            slo[b] += __shfl_xor_sync(0xffffffffu, slo[b], 1);
            slo[b] += __shfl_xor_sync(0xffffffffu, slo[b], 2);
            shi[b] += __shfl_xor_sync(0xffffffffu, shi[b], 1);
            shi[b] += __shfl_xor_sync(0xffffffffu, shi[b], 2);
        }
        if ((lane & 3) == 0) {
#pragma unroll
            for (int b = 0; b < CB; b++) {
                atomicAdd(&g_den[b * CL + row_lo], slo[b]);
                atomicAdd(&g_den[b * CL + row_hi], shi[b]);
            }
        }
    }
}

// ---------------------------------------------------------------------------
// FP16 tensor-core GEMM (cp.async 3-stage + ldmatrix)
// OPT bits: 1=+bias, 2=relu, 32=half C out, 64=raw HALF partial out (to Ch)
// ---------------------------------------------------------------------------
template <int OPT, int SPLIT>
__global__ void __launch_bounds__(256, 2) k_hgemm(
    const __half* __restrict__ A, const __half* __restrict__ B,
    const float* __restrict__ bias,
    float* __restrict__ C, __half* __restrict__ Ch,
    int N, int K, size_t sB, size_t sC)
{
    extern __shared__ __align__(128) char smem[];
    const int tid = threadIdx.x;
    const int lane = tid & 31;
    const int wid = tid >> 5;
    const int wr = wid >> 2;
    const int wc = wid & 3;

    const int z = blockIdx.z;
    const int bb = z / SPLIT;
    const int sp = z % SPLIT;
    const int kt = K / SPLIT;
    const int ksta = sp * kt;
    const size_t czoff = (size_t)z * sC;

    const int m0 = blockIdx.y * 128;
    const int n0 = blockIdx.x * 128;

    uint32_t sbase = (uint32_t)__cvta_generic_to_shared(smem);

    const __half* ag[4];
    const __half* bg[4];
    uint32_t asmo[4], bsmo[4];
#pragma unroll
    for (int i = 0; i < 4; i++) {
        int cid = tid + i * 256;
        int am = cid >> 3, kc = cid & 7;
        ag[i] = A + (size_t)(m0 + am) * K + ksta + kc * 8;
        asmo[i] = am * 128 + ((kc ^ (am & 7)) << 4);
        int bk = cid >> 4, bc = cid & 15;
        bg[i] = B + (size_t)bb * sB + (size_t)(ksta + bk) * N + n0 + bc * 8;
        bsmo[i] = 16384 + bk * 256 + (((bc & 8) | ((bc & 7) ^ (bk & 7))) << 4);
    }

    float acc[4][4][4];
#pragma unroll
    for (int i = 0; i < 4; i++)
#pragma unroll
        for (int j = 0; j < 4; j++)
#pragma unroll
            for (int q = 0; q < 4; q++) acc[i][j][q] = 0.f;

    const int NC = kt >> 6;

    {
        uint32_t sb = sbase;
#pragma unroll
        for (int i = 0; i < 4; i++) cpasync16(sb + asmo[i], ag[i]);
#pragma unroll
        for (int i = 0; i < 4; i++) cpasync16(sb + bsmo[i], bg[i]);
    }
    CP_COMMIT();
    {
        uint32_t sb = sbase + 32768;
#pragma unroll
        for (int i = 0; i < 4; i++) cpasync16(sb + asmo[i], ag[i] + 64);
#pragma unroll
        for (int i = 0; i < 4; i++) cpasync16(sb + bsmo[i], bg[i] + (size_t)64 * N);
    }
    CP_COMMIT();

    const int am8 = (lane & 7) + (((lane >> 3) & 1) << 3);
    const int kq  = lane >> 4;

    for (int c = 0; c < NC; c++) {
        CP_WAIT1();
        __syncthreads();
        if (c + 2 < NC) {
            uint32_t sb = sbase + ((c + 2) % 3) * 32768;
            const int ko = (c + 2) * 64;
#pragma unroll
            for (int i = 0; i < 4; i++) cpasync16(sb + asmo[i], ag[i] + ko);
#pragma unroll
            for (int i = 0; i < 4; i++) cpasync16(sb + bsmo[i], bg[i] + (size_t)ko * N);
        }
        CP_COMMIT();

        uint32_t abase = sbase + (c % 3) * 32768;
        uint32_t bbase = abase + 16384;
#pragma unroll
        for (int ks = 0; ks < 4; ks++) {
            uint4 af[4];
#pragma unroll
            for (int i = 0; i < 4; i++) {
                int m = wr * 64 + i * 16 + am8;
                uint32_t ad = abase + m * 128 + ((((ks * 2 + kq)) ^ (lane & 7)) << 4);
                ldsm4(af[i], ad);
            }
            uint2 bf[4];
#pragma unroll
            for (int jj = 0; jj < 2; jj++) {
                int k = ks * 16 + am8;
                int c2 = wc * 4 + jj * 2 + kq;
                uint32_t bd = bbase + k * 256 +
                              (((c2 & 8) | ((c2 & 7) ^ (lane & 7))) << 4);
                uint32_t r0, r1, r2, r3;
                ldsm4t(r0, r1, r2, r3, bd);
                bf[2 * jj]     = make_uint2(r0, r1);
                bf[2 * jj + 1] = make_uint2(r2, r3);
            }
#pragma unroll
            for (int i = 0; i < 4; i++)
#pragma unroll
                for (int j = 0; j < 4; j++)
                    mma16816(acc[i][j], af[i], bf[j]);
        }
    }

    const int rbase = m0 + wr * 64;
    const int cbase = n0 + wc * 32;
#pragma unroll
    for (int i = 0; i < 4; i++) {
        int row_lo = rbase + i * 16 + (lane >> 2);
        int row_hi = row_lo + 8;
#pragma unroll
        for (int j = 0; j < 4; j++) {
            int col = cbase + j * 8 + (lane & 3) * 2;
            float2 lo = make_float2(acc[i][j][0], acc[i][j][1]);
            float2 hi = make_float2(acc[i][j][2], acc[i][j][3]);
            if (OPT & 64) {   // raw half partial out
                *(uint32_t*)&Ch[czoff + (size_t)row_lo * N + col] = packh2(lo.x, lo.y);
                *(uint32_t*)&Ch[czoff + (size_t)row_hi * N + col] = packh2(hi.x, hi.y);
                continue;
            }
            if (OPT & 1) {
                float2 bbv = *(const float2*)&bias[col];
                lo.x += bbv.x; lo.y += bbv.y;
                hi.x += bbv.x; hi.y += bbv.y;
            }
            if (OPT & 2) {
                lo.x = fmaxf(lo.x, 0.f); lo.y = fmaxf(lo.y, 0.f);
                hi.x = fmaxf(hi.x, 0.f); hi.y = fmaxf(hi.y, 0.f);
            }
            if (OPT & 32) {
                *(uint32_t*)&Ch[czoff + (size_t)row_lo * N + col] = packh2(lo.x, lo.y);
                *(uint32_t*)&Ch[czoff + (size_t)row_hi * N + col] = packh2(hi.x, hi.y);
            } else {
                *(float2*)&C[czoff + (size_t)row_lo * N + col] = lo;
                *(float2*)&C[czoff + (size_t)row_hi * N + col] = hi;
            }
        }
    }
}

// ---------------------------------------------------------------------------
// Warp-per-row reduce+LN kernels (half partials)
// ---------------------------------------------------------------------------
__device__ __forceinline__ float warp_sum(float v) {
#pragma unroll
    for (int o = 16; o > 0; o >>= 1) v += __shfl_xor_sync(0xffffffffu, v, o);
    return v;
}

// v = (part0+part1)/den + x  -> LN(g1,be1) -> Hn (f32) + Hnh (half)
__global__ void __launch_bounds__(256) k_red_ln1(
    const float* __restrict__ x,
    const float* __restrict__ gw, const float* __restrict__ bw) {
    int warp = threadIdx.x >> 5, lane = threadIdx.x & 31;
    int r = blockIdx.x * 8 + warp;            // 0..CB*CL-1
    int b = r >> 11, m = r & (CL - 1);
    size_t zs = (size_t)CL * CD;
    size_t po = (size_t)(b * 2) * zs + (size_t)m * CD + lane * 8;
    uint4 pa = *(const uint4*)&g_parth[po];        // 8 halves (slice 0)
    uint4 pb = *(const uint4*)&g_parth[po + zs];   // 8 halves (slice 1)
    float2 a0 = h2f(pa.x), a1 = h2f(pa.y), a2 = h2f(pa.z), a3 = h2f(pa.w);
    float2 c0 = h2f(pb.x), c1 = h2f(pb.y), c2 = h2f(pb.z), c3 = h2f(pb.w);
    float invd = 1.f / g_den[b * CL + m];
    size_t xo = (size_t)r * CD + lane * 8;
    float4 x0 = *(const float4*)&x[xo];
    float4 x1 = *(const float4*)&x[xo + 4];

    float v[8];
    v[0] = (a0.x + c0.x) * invd + x0.x;
    v[1] = (a0.y + c0.y) * invd + x0.y;
    v[2] = (a1.x + c1.x) * invd + x0.z;
    v[3] = (a1.y + c1.y) * invd + x0.w;
    v[4] = (a2.x + c2.x) * invd + x1.x;
    v[5] = (a2.y + c2.y) * invd + x1.y;
    v[6] = (a3.x + c3.x) * invd + x1.z;
    v[7] = (a3.y + c3.y) * invd + x1.w;

    float s = 0.f;
#pragma unroll
    for (int i = 0; i < 8; i++) s += v[i];
    float mu = warp_sum(s) * (1.f / CD);
    float s2 = 0.f;
#pragma unroll
    for (int i = 0; i < 8; i++) {
        v[i] -= mu;
        s2 += v[i] * v[i];
    }
    float rstd = rsqrtf(warp_sum(s2) * (1.f / CD) + 1e-5f);

    float4 g0 = *(const float4*)&gw[lane * 8];
    float4 g1v = *(const float4*)&gw[lane * 8 + 4];
    float4 b0 = *(const float4*)&bw[lane * 8];
    float4 b1v = *(const float4*)&bw[lane * 8 + 4];
    float y[8];
    y[0] = v[0] * rstd * g0.x + b0.x;  y[1] = v[1] * rstd * g0.y + b0.y;
    y[2] = v[2] * rstd * g0.z + b0.z;  y[3] = v[3] * rstd * g0.w + b0.w;
    y[4] = v[4] * rstd * g1v.x + b1v.x; y[5] = v[5] * rstd * g1v.y + b1v.y;
    y[6] = v[6] * rstd * g1v.z + b1v.z; y[7] = v[7] * rstd * g1v.w + b1v.w;

    *(float4*)&g_Hn[xo]     = make_float4(y[0], y[1], y[2], y[3]);
    *(float4*)&g_Hn[xo + 4] = make_float4(y[4], y[5], y[6], y[7]);
    uint4 o;
    o.x = packh2(y[0], y[1]); o.y = packh2(y[2], y[3]);
    o.z = packh2(y[4], y[5]); o.w = packh2(y[6], y[7]);
    *(uint4*)&g_Hnh[xo] = o;
}

// v = part0+part1 + b2 + Hn -> LN(g2,be2) -> out
__global__ void __launch_bounds__(256) k_red_ln2(
    const float* __restrict__ b2,
    const float* __restrict__ gw, const float* __restrict__ bw,
    float* __restrict__ out) {
    int warp = threadIdx.x >> 5, lane = threadIdx.x & 31;
    int r = blockIdx.x * 8 + warp;
    size_t zs = (size_t)CB * CL * CD;
    size_t rowoff = (size_t)r * CD + lane * 8;
    uint4 pa = *(const uint4*)&g_parth[rowoff];
    uint4 pb = *(const uint4*)&g_parth[rowoff + zs];
    float2 a0 = h2f(pa.x), a1 = h2f(pa.y), a2 = h2f(pa.z), a3 = h2f(pa.w);
    float2 c0 = h2f(pb.x), c1 = h2f(pb.y), c2 = h2f(pb.z), c3 = h2f(pb.w);
    float4 h0 = *(const float4*)&g_Hn[rowoff];
    float4 h1 = *(const float4*)&g_Hn[rowoff + 4];
    float4 bb0 = *(const float4*)&b2[lane * 8];
    float4 bb1 = *(const float4*)&b2[lane * 8 + 4];

    float v[8];
    v[0] = a0.x + c0.x + bb0.x + h0.x;
    v[1] = a0.y + c0.y + bb0.y + h0.y;
    v[2] = a1.x + c1.x + bb0.z + h0.z;
    v[3] = a1.y + c1.y + bb0.w + h0.w;
    v[4] = a2.x + c2.x + bb1.x + h1.x;
    v[5] = a2.y + c2.y + bb1.y + h1.y;
    v[6] = a3.x + c3.x + bb1.z + h1.z;
    v[7] = a3.y + c3.y + bb1.w + h1.w;

    float s = 0.f;
#pragma unroll
    for (int i = 0; i < 8; i++) s += v[i];
    float mu = warp_sum(s) * (1.f / CD);
    float s2 = 0.f;
#pragma unroll
    for (int i = 0; i < 8; i++) {
        v[i] -= mu;
        s2 += v[i] * v[i];
    }
    float rstd = rsqrtf(warp_sum(s2) * (1.f / CD) + 1e-5f);

    float4 g0 = *(const float4*)&gw[lane * 8];
    float4 g1v = *(const float4*)&gw[lane * 8 + 4];
    float4 w0 = *(const float4*)&bw[lane * 8];
    float4 w1 = *(const float4*)&bw[lane * 8 + 4];
    *(float4*)&out[rowoff] = make_float4(
        v[0] * rstd * g0.x + w0.x, v[1] * rstd * g0.y + w0.y,
        v[2] * rstd * g0.z + w0.z, v[3] * rstd * g0.w + w0.w);
    *(float4*)&out[rowoff + 4] = make_float4(
        v[4] * rstd * g1v.x + w1.x, v[5] * rstd * g1v.y + w1.y,
        v[6] * rstd * g1v.z + w1.z, v[7] * rstd * g1v.w + w1.w);
}

// ---------------------------------------------------------------------------
// kernel_launch
// ---------------------------------------------------------------------------
extern "C" void kernel_launch(void* const* d_in, const int* in_sizes, int n_in,
                              void* d_out, int out_size) {
    const float* x    = (const float*)d_in[0];
    const int*   mask = (const int*)  d_in[1];
    const float* W1   = (const float*)d_in[2];
    const float* b1   = (const float*)d_in[3];
    const float* W2   = (const float*)d_in[4];
    const float* b2   = (const float*)d_in[5];
    const float* g1   = (const float*)d_in[6];
    const float* be1  = (const float*)d_in[7];
    const float* g2   = (const float*)d_in[8];
    const float* be2  = (const float*)d_in[9];
    float* out = (float*)d_out;

    __half *pP, *pHnh, *pH1h, *pParth, *pW1h, *pW2h;
    cudaGetSymbolAddress((void**)&pP,     g_P);
    cudaGetSymbolAddress((void**)&pParth, g_parth);
    cudaGetSymbolAddress((void**)&pHnh,   g_Hnh);
    cudaGetSymbolAddress((void**)&pH1h,   g_H1h);
    cudaGetSymbolAddress((void**)&pW1h,   g_W1h);
    cudaGetSymbolAddress((void**)&pW2h,   g_W2h);

    const int DSMEM = 3 * 32768;
    cudaFuncSetAttribute(k_hgemm<64, 2>, cudaFuncAttributeMaxDynamicSharedMemorySize, DSMEM);
    cudaFuncSetAttribute(k_hgemm<35, 1>, cudaFuncAttributeMaxDynamicSharedMemorySize, DSMEM);

    // 1) token mean (half) + zero denominators
    k_mean<<<(CL * CDK + 255) / 256, 256>>>(x);
    // 2) scores (tensor core, fused denominators) + all half conversions
    k_scores_conv<<<1536, 256>>>(mask, x, W1, W2);

    // 3) GEMM1 split-K2: parth[b*2+s] = P[:, ks] @ xh_b[ks, :]  (half partials)
    {
        __half* pxh;
        cudaGetSymbolAddress((void**)&pxh, g_xh);
        k_hgemm<64, 2><<<dim3(CD / 128, CL / 128, CB * 2), 256, DSMEM>>>(
            pP, pxh, nullptr, nullptr, pParth,
            CD, CL, (size_t)CL * CD, (size_t)CL * CD);
    }

    // 4) reduce + /den + residual(x) + LN1 -> Hn, Hnh
    k_red_ln1<<<CB * CL / 8, 256>>>(x, g1, be1);

    // 5) H1h = half(relu(Hn @ W1 + b1))   OPT = 1|2|32
    k_hgemm<35, 1><<<dim3(CF / 128, (CB * CL) / 128, 1), 256, DSMEM>>>(
        pHnh, pW1h, b1, nullptr, pH1h,
        CF, CD, 0, 0);

    // 6) GEMM3 split-K2: parth[s] = H1h[:, ks] @ W2h[ks, :]  (half partials)
    k_hgemm<64, 2><<<dim3(CD / 128, (CB * CL) / 128, 2), 256, DSMEM>>>(
        pH1h, pW2h, nullptr, nullptr, pParth,
        CD, CF, 0, (size_t)CB * CL * CD);

    // 7) reduce + bias + residual(Hn) + LN2 -> out
    k_red_ln2<<<CB * CL / 8, 256>>>(b2, g2, be2, out);
}

// round 17
// speedup vs baseline: 1.4972x; 1.4972x over previous
#include <cuda_runtime.h>
#include <cuda_fp16.h>
#include <math.h>
#include <stdint.h>

// Problem constants (fixed by reference setup_inputs)
#define CB 4
#define CL 2048
#define CD 256
#define CH 8
#define CDK 32
#define CF 1024

// ---------------------------------------------------------------------------
// Scratch (device globals: allocation-free per harness rules)
// ---------------------------------------------------------------------------
__device__ __align__(16) __half g_mh[CL * CDK];                  // 128 KB
__device__ __align__(16) __half g_P[(size_t)CL * CL];            // 8 MB : exp(scores)
__device__ __align__(16) float  g_den[CB * CL];                  // 32 KB
__device__ __align__(16) __half g_parth[(size_t)4 * 1024 * 1024];// 8 MB : half partials
__device__ __align__(16) float  g_Hn[(size_t)CB * CL * CD];      // 8 MB
__device__ __align__(16) __half g_Hnh[(size_t)CB * CL * CD];     // 4 MB
__device__ __align__(16) __half g_H1h[(size_t)CB * CL * CF];     // 16 MB
__device__ __align__(16) __half g_xh[(size_t)CB * CL * CD];      // 4 MB : masked x, half
__device__ __align__(16) __half g_W1h[(size_t)CD * CF];          // 512 KB
__device__ __align__(16) __half g_W2h[(size_t)CF * CD];          // 512 KB

__device__ __forceinline__ uint32_t packh2(float lo, float hi) {
    __half2 h = __floats2half2_rn(lo, hi);
    return *(uint32_t*)&h;
}
__device__ __forceinline__ float2 h2f(uint32_t u) {
    return __half22float2(*(__half2*)&u);
}

// ---------------------------------------------------------------------------
// mh[l, d] = half( mean over (b, h) of x[b, l, h*32 + d] ); also zeros g_den
// ---------------------------------------------------------------------------
__global__ void k_mean(const float* __restrict__ x) {
    int idx = blockIdx.x * blockDim.x + threadIdx.x;
    if (idx < CB * CL) g_den[idx] = 0.f;
    if (idx >= CL * CDK) return;
    int l = idx / CDK;
    int d = idx % CDK;
    float s = 0.f;
#pragma unroll
    for (int b = 0; b < CB; b++)
#pragma unroll
        for (int h = 0; h < CH; h++)
            s += x[((size_t)(b * CL) + l) * CD + h * CDK + d];
    g_mh[idx] = __float2half_rn(s * (1.f / 32.f));
}

// ---------------------------------------------------------------------------
// mma / ldmatrix / cp.async helpers
// ---------------------------------------------------------------------------
__device__ __forceinline__ void mma16816(float* d, const uint4& a, const uint2& b) {
    asm volatile(
        "mma.sync.aligned.m16n8k16.row.col.f32.f16.f16.f32 "
        "{%0,%1,%2,%3}, {%4,%5,%6,%7}, {%8,%9}, {%0,%1,%2,%3};"
        : "+f"(d[0]), "+f"(d[1]), "+f"(d[2]), "+f"(d[3])
        : "r"(a.x), "r"(a.y), "r"(a.z), "r"(a.w), "r"(b.x), "r"(b.y));
}
__device__ __forceinline__ void ldsm4(uint4& d, uint32_t a) {
    asm volatile("ldmatrix.sync.aligned.m8n8.x4.shared.b16 {%0,%1,%2,%3}, [%4];"
        : "=r"(d.x), "=r"(d.y), "=r"(d.z), "=r"(d.w) : "r"(a));
}
__device__ __forceinline__ void ldsm4t(uint32_t& r0, uint32_t& r1,
                                       uint32_t& r2, uint32_t& r3, uint32_t a) {
    asm volatile("ldmatrix.sync.aligned.m8n8.x4.trans.shared.b16 {%0,%1,%2,%3}, [%4];"
        : "=r"(r0), "=r"(r1), "=r"(r2), "=r"(r3) : "r"(a));
}
__device__ __forceinline__ void cpasync16(uint32_t s, const void* g) {
    asm volatile("cp.async.cg.shared.global [%0], [%1], 16;" :: "r"(s), "l"(g));
}
#define CP_COMMIT() asm volatile("cp.async.commit_group;" ::: "memory")
#define CP_WAIT1()  asm volatile("cp.async.wait_group 1;" ::: "memory")

// ---------------------------------------------------------------------------
// Tensor-core scores: P = exp(sin^2(clip(mh @ mh^T)/2)) (half) + fused
// masked row-sum denominators (atomicAdd into g_den).
// ---------------------------------------------------------------------------
__global__ void __launch_bounds__(256) k_scores_mma(const int* __restrict__ mask) {
    __shared__ __align__(16) __half sA[128 * 40];   // 80B row stride
    __shared__ __align__(16) __half sB[128 * 40];
    __shared__ float mk[CB][128];

    const int tid = threadIdx.x;
    const int lane = tid & 31;
    const int wid = tid >> 5;
    const int wr = wid >> 2;
    const int wc = wid & 3;
    const int i0 = blockIdx.y * 128;
    const int j0 = blockIdx.x * 128;

#pragma unroll
    for (int u = 0; u < 2; u++) {
        int cid = tid + u * 256;
        int r = cid >> 2, c = cid & 3;
        *(uint4*)&sA[r * 40 + c * 8] = *(const uint4*)&g_mh[(i0 + r) * CDK + c * 8];
        *(uint4*)&sB[r * 40 + c * 8] = *(const uint4*)&g_mh[(j0 + r) * CDK + c * 8];
    }
    {
        int b = tid >> 6, j = (tid & 63) * 2;
        mk[b][j]     = (mask[b * CL + j0 + j] != 0) ? 1.f : 0.f;
        mk[b][j + 1] = (mask[b * CL + j0 + j + 1] != 0) ? 1.f : 0.f;
    }
    __syncthreads();

    uint32_t aS = (uint32_t)__cvta_generic_to_shared(sA);
    uint32_t bS = (uint32_t)__cvta_generic_to_shared(sB);

    const int am8 = (lane & 7) + (((lane >> 3) & 1) << 3);
    const int kq  = lane >> 4;

    float acc[4][4][4];
#pragma unroll
    for (int i = 0; i < 4; i++)
#pragma unroll
        for (int j = 0; j < 4; j++)
#pragma unroll
            for (int q = 0; q < 4; q++) acc[i][j][q] = 0.f;

#pragma unroll
    for (int ks = 0; ks < 2; ks++) {
        uint4 af[4];
#pragma unroll
        for (int i = 0; i < 4; i++) {
            int m = wr * 64 + i * 16 + am8;
            ldsm4(af[i], aS + m * 80 + (ks * 2 + kq) * 16);
        }
        uint2 bf[4];
#pragma unroll
        for (int jj = 0; jj < 2; jj++) {
            int n = wc * 32 + jj * 16 + am8;
            uint4 t;
            ldsm4(t, bS + n * 80 + (ks * 2 + kq) * 16);
            bf[jj * 2]     = make_uint2(t.x, t.z);
            bf[jj * 2 + 1] = make_uint2(t.y, t.w);
        }
#pragma unroll
        for (int i = 0; i < 4; i++)
#pragma unroll
            for (int j = 0; j < 4; j++)
                mma16816(acc[i][j], af[i], bf[j]);
    }

    const float PI = 3.14159265358979323846f;
#pragma unroll
    for (int i = 0; i < 4; i++) {
        int row_lo = i0 + wr * 64 + i * 16 + (lane >> 2);
        int row_hi = row_lo + 8;
        float slo[CB] = {0.f, 0.f, 0.f, 0.f};
        float shi[CB] = {0.f, 0.f, 0.f, 0.f};
#pragma unroll
        for (int j = 0; j < 4; j++) {
            int cl = wc * 32 + j * 8 + (lane & 3) * 2;
            float p0 = __expf(0.5f * (1.f - __cosf(fminf(fmaxf(acc[i][j][0], -PI), PI))));
            float p1 = __expf(0.5f * (1.f - __cosf(fminf(fmaxf(acc[i][j][1], -PI), PI))));
            float p2 = __expf(0.5f * (1.f - __cosf(fminf(fmaxf(acc[i][j][2], -PI), PI))));
            float p3 = __expf(0.5f * (1.f - __cosf(fminf(fmaxf(acc[i][j][3], -PI), PI))));
            uint32_t wlo = packh2(p0, p1);
            uint32_t whi = packh2(p2, p3);
            *(uint32_t*)&g_P[(size_t)row_lo * CL + j0 + cl] = wlo;
            *(uint32_t*)&g_P[(size_t)row_hi * CL + j0 + cl] = whi;
            float2 flo = h2f(wlo);
            float2 fhi = h2f(whi);
#pragma unroll
            for (int b = 0; b < CB; b++) {
                slo[b] += flo.x * mk[b][cl] + flo.y * mk[b][cl + 1];
                shi[b] += fhi.x * mk[b][cl] + fhi.y * mk[b][cl + 1];
            }
        }
#pragma unroll
        for (int b = 0; b < CB; b++) {
            slo[b] += __shfl_xor_sync(0xffffffffu, slo[b], 1);
            slo[b] += __shfl_xor_sync(0xffffffffu, slo[b], 2);
            shi[b] += __shfl_xor_sync(0xffffffffu, shi[b], 1);
            shi[b] += __shfl_xor_sync(0xffffffffu, shi[b], 2);
        }
        if ((lane & 3) == 0) {
#pragma unroll
            for (int b = 0; b < CB; b++) {
                atomicAdd(&g_den[b * CL + row_lo], slo[b]);
                atomicAdd(&g_den[b * CL + row_hi], shi[b]);
            }
        }
    }
}

// ---------------------------------------------------------------------------
// Merged half conversions: blocks [0,1024) -> xh (masked), [1024,1152) -> W1h,
// [1152,1280) -> W2h. 8 elems / thread.
// ---------------------------------------------------------------------------
__global__ void k_convert(const float* __restrict__ x, const int* __restrict__ mask,
                          const float* __restrict__ W1, const float* __restrict__ W2) {
    int bid = blockIdx.x;
    if (bid < 1024) {
        size_t e = ((size_t)bid * 256 + threadIdx.x) * 8;
        int msk = mask[e >> 8];
        float4 v0 = *(const float4*)&x[e];
        float4 v1 = *(const float4*)&x[e + 4];
        if (!msk) {
            v0 = make_float4(0.f, 0.f, 0.f, 0.f);
            v1 = make_float4(0.f, 0.f, 0.f, 0.f);
        }
        uint4 o;
        o.x = packh2(v0.x, v0.y); o.y = packh2(v0.z, v0.w);
        o.z = packh2(v1.x, v1.y); o.w = packh2(v1.z, v1.w);
        *(uint4*)&g_xh[e] = o;
    } else {
        const float* src = (bid < 1152) ? W1 : W2;
        __half* dst = (bid < 1152) ? g_W1h : g_W2h;
        int lb = (bid < 1152) ? bid - 1024 : bid - 1152;
        size_t e = ((size_t)lb * 256 + threadIdx.x) * 8;
        float4 v0 = *(const float4*)&src[e];
        float4 v1 = *(const float4*)&src[e + 4];
        uint4 o;
        o.x = packh2(v0.x, v0.y); o.y = packh2(v0.z, v0.w);
        o.z = packh2(v1.x, v1.y); o.w = packh2(v1.z, v1.w);
        *(uint4*)&dst[e] = o;
    }
}

// ---------------------------------------------------------------------------
// FP16 tensor-core GEMM (cp.async 3-stage + ldmatrix)
// OPT bits: 1=+bias, 2=relu, 32=half C out, 64=raw HALF partial out (to Ch)
// ---------------------------------------------------------------------------
template <int OPT, int SPLIT>
__global__ void __launch_bounds__(256, 2) k_hgemm(
    const __half* __restrict__ A, const __half* __restrict__ B,
    const float* __restrict__ bias,
    float* __restrict__ C, __half* __restrict__ Ch,
    int N, int K, size_t sB, size_t sC)
{
    extern __shared__ __align__(128) char smem[];
    const int tid = threadIdx.x;
    const int lane = tid & 31;
    const int wid = tid >> 5;
    const int wr = wid >> 2;
    const int wc = wid & 3;

    const int z = blockIdx.z;
    const int bb = z / SPLIT;
    const int sp = z % SPLIT;
    const int kt = K / SPLIT;
    const int ksta = sp * kt;
    const size_t czoff = (size_t)z * sC;

    const int m0 = blockIdx.y * 128;
    const int n0 = blockIdx.x * 128;

    uint32_t sbase = (uint32_t)__cvta_generic_to_shared(smem);

    const __half* ag[4];
    const __half* bg[4];
    uint32_t asmo[4], bsmo[4];
#pragma unroll
    for (int i = 0; i < 4; i++) {
        int cid = tid + i * 256;
        int am = cid >> 3, kc = cid & 7;
        ag[i] = A + (size_t)(m0 + am) * K + ksta + kc * 8;
        asmo[i] = am * 128 + ((kc ^ (am & 7)) << 4);
        int bk = cid >> 4, bc = cid & 15;
        bg[i] = B + (size_t)bb * sB + (size_t)(ksta + bk) * N + n0 + bc * 8;
        bsmo[i] = 16384 + bk * 256 + (((bc & 8) | ((bc & 7) ^ (bk & 7))) << 4);
    }

    float acc[4][4][4];
#pragma unroll
    for (int i = 0; i < 4; i++)
#pragma unroll
        for (int j = 0; j < 4; j++)
#pragma unroll
            for (int q = 0; q < 4; q++) acc[i][j][q] = 0.f;

    const int NC = kt >> 6;

    {
        uint32_t sb = sbase;
#pragma unroll
        for (int i = 0; i < 4; i++) cpasync16(sb + asmo[i], ag[i]);
#pragma unroll
        for (int i = 0; i < 4; i++) cpasync16(sb + bsmo[i], bg[i]);
    }
    CP_COMMIT();
    {
        uint32_t sb = sbase + 32768;
#pragma unroll
        for (int i = 0; i < 4; i++) cpasync16(sb + asmo[i], ag[i] + 64);
#pragma unroll
        for (int i = 0; i < 4; i++) cpasync16(sb + bsmo[i], bg[i] + (size_t)64 * N);
    }
    CP_COMMIT();

    const int am8 = (lane & 7) + (((lane >> 3) & 1) << 3);
    const int kq  = lane >> 4;

    for (int c = 0; c < NC; c++) {
        CP_WAIT1();
        __syncthreads();
        if (c + 2 < NC) {
            uint32_t sb = sbase + ((c + 2) % 3) * 32768;
            const int ko = (c + 2) * 64;
#pragma unroll
            for (int i = 0; i < 4; i++) cpasync16(sb + asmo[i], ag[i] + ko);
#pragma unroll
            for (int i = 0; i < 4; i++) cpasync16(sb + bsmo[i], bg[i] + (size_t)ko * N);
        }
        CP_COMMIT();

        uint32_t abase = sbase + (c % 3) * 32768;
        uint32_t bbase = abase + 16384;
#pragma unroll
        for (int ks = 0; ks < 4; ks++) {
            uint4 af[4];
#pragma unroll
            for (int i = 0; i < 4; i++) {
                int m = wr * 64 + i * 16 + am8;
                uint32_t ad = abase + m * 128 + ((((ks * 2 + kq)) ^ (lane & 7)) << 4);
                ldsm4(af[i], ad);
            }
            uint2 bf[4];
#pragma unroll
            for (int jj = 0; jj < 2; jj++) {
                int k = ks * 16 + am8;
                int c2 = wc * 4 + jj * 2 + kq;
                uint32_t bd = bbase + k * 256 +
                              (((c2 & 8) | ((c2 & 7) ^ (lane & 7))) << 4);
                uint32_t r0, r1, r2, r3;
                ldsm4t(r0, r1, r2, r3, bd);
                bf[2 * jj]     = make_uint2(r0, r1);
                bf[2 * jj + 1] = make_uint2(r2, r3);
            }
#pragma unroll
            for (int i = 0; i < 4; i++)
#pragma unroll
                for (int j = 0; j < 4; j++)
                    mma16816(acc[i][j], af[i], bf[j]);
        }
    }

    const int rbase = m0 + wr * 64;
    const int cbase = n0 + wc * 32;
#pragma unroll
    for (int i = 0; i < 4; i++) {
        int row_lo = rbase + i * 16 + (lane >> 2);
        int row_hi = row_lo + 8;
#pragma unroll
        for (int j = 0; j < 4; j++) {
            int col = cbase + j * 8 + (lane & 3) * 2;
            float2 lo = make_float2(acc[i][j][0], acc[i][j][1]);
            float2 hi = make_float2(acc[i][j][2], acc[i][j][3]);
            if (OPT & 64) {   // raw half partial out
                *(uint32_t*)&Ch[czoff + (size_t)row_lo * N + col] = packh2(lo.x, lo.y);
                *(uint32_t*)&Ch[czoff + (size_t)row_hi * N + col] = packh2(hi.x, hi.y);
                continue;
            }
            if (OPT & 1) {
                float2 bbv = *(const float2*)&bias[col];
                lo.x += bbv.x; lo.y += bbv.y;
                hi.x += bbv.x; hi.y += bbv.y;
            }
            if (OPT & 2) {
                lo.x = fmaxf(lo.x, 0.f); lo.y = fmaxf(lo.y, 0.f);
                hi.x = fmaxf(hi.x, 0.f); hi.y = fmaxf(hi.y, 0.f);
            }
            if (OPT & 32) {
                *(uint32_t*)&Ch[czoff + (size_t)row_lo * N + col] = packh2(lo.x, lo.y);
                *(uint32_t*)&Ch[czoff + (size_t)row_hi * N + col] = packh2(hi.x, hi.y);
            } else {
                *(float2*)&C[czoff + (size_t)row_lo * N + col] = lo;
                *(float2*)&C[czoff + (size_t)row_hi * N + col] = hi;
            }
        }
    }
}

// ---------------------------------------------------------------------------
// Warp-per-row reduce+LN kernels (half partials, shfl-only reductions)
// ---------------------------------------------------------------------------
__device__ __forceinline__ float warp_sum(float v) {
#pragma unroll
    for (int o = 16; o > 0; o >>= 1) v += __shfl_xor_sync(0xffffffffu, v, o);
    return v;
}

// v = (part0+part1)/den + x  -> LN(g1,be1) -> Hn (f32) + Hnh (half)
__global__ void __launch_bounds__(256) k_red_ln1(
    const float* __restrict__ x,
    const float* __restrict__ gw, const float* __restrict__ bw) {
    int warp = threadIdx.x >> 5, lane = threadIdx.x & 31;
    int r = blockIdx.x * 8 + warp;            // 0..CB*CL-1
    int b = r >> 11, m = r & (CL - 1);
    size_t zs = (size_t)CL * CD;
    size_t po = (size_t)(b * 2) * zs + (size_t)m * CD + lane * 8;
    uint4 pa = *(const uint4*)&g_parth[po];        // 8 halves (slice 0)
    uint4 pb = *(const uint4*)&g_parth[po + zs];   // 8 halves (slice 1)
    float2 a0 = h2f(pa.x), a1 = h2f(pa.y), a2 = h2f(pa.z), a3 = h2f(pa.w);
    float2 c0 = h2f(pb.x), c1 = h2f(pb.y), c2 = h2f(pb.z), c3 = h2f(pb.w);
    float invd = 1.f / g_den[b * CL + m];
    size_t xo = (size_t)r * CD + lane * 8;
    float4 x0 = *(const float4*)&x[xo];
    float4 x1 = *(const float4*)&x[xo + 4];

    float v[8];
    v[0] = (a0.x + c0.x) * invd + x0.x;
    v[1] = (a0.y + c0.y) * invd + x0.y;
    v[2] = (a1.x + c1.x) * invd + x0.z;
    v[3] = (a1.y + c1.y) * invd + x0.w;
    v[4] = (a2.x + c2.x) * invd + x1.x;
    v[5] = (a2.y + c2.y) * invd + x1.y;
    v[6] = (a3.x + c3.x) * invd + x1.z;
    v[7] = (a3.y + c3.y) * invd + x1.w;

    float s = 0.f;
#pragma unroll
    for (int i = 0; i < 8; i++) s += v[i];
    float mu = warp_sum(s) * (1.f / CD);
    float s2 = 0.f;
#pragma unroll
    for (int i = 0; i < 8; i++) {
        v[i] -= mu;
        s2 += v[i] * v[i];
    }
    float rstd = rsqrtf(warp_sum(s2) * (1.f / CD) + 1e-5f);

    float4 g0 = *(const float4*)&gw[lane * 8];
    float4 g1v = *(const float4*)&gw[lane * 8 + 4];
    float4 b0 = *(const float4*)&bw[lane * 8];
    float4 b1v = *(const float4*)&bw[lane * 8 + 4];
    float y[8];
    y[0] = v[0] * rstd * g0.x + b0.x;  y[1] = v[1] * rstd * g0.y + b0.y;
    y[2] = v[2] * rstd * g0.z + b0.z;  y[3] = v[3] * rstd * g0.w + b0.w;
    y[4] = v[4] * rstd * g1v.x + b1v.x; y[5] = v[5] * rstd * g1v.y + b1v.y;
    y[6] = v[6] * rstd * g1v.z + b1v.z; y[7] = v[7] * rstd * g1v.w + b1v.w;

    *(float4*)&g_Hn[xo]     = make_float4(y[0], y[1], y[2], y[3]);
    *(float4*)&g_Hn[xo + 4] = make_float4(y[4], y[5], y[6], y[7]);
    uint4 o;
    o.x = packh2(y[0], y[1]); o.y = packh2(y[2], y[3]);
    o.z = packh2(y[4], y[5]); o.w = packh2(y[6], y[7]);
    *(uint4*)&g_Hnh[xo] = o;
}

// v = part0+part1 + b2 + Hn -> LN(g2,be2) -> out
__global__ void __launch_bounds__(256) k_red_ln2(
    const float* __restrict__ b2,
    const float* __restrict__ gw, const float* __restrict__ bw,
    float* __restrict__ out) {
    int warp = threadIdx.x >> 5, lane = threadIdx.x & 31;
    int r = blockIdx.x * 8 + warp;
    size_t zs = (size_t)CB * CL * CD;
    size_t rowoff = (size_t)r * CD + lane * 8;
    uint4 pa = *(const uint4*)&g_parth[rowoff];
    uint4 pb = *(const uint4*)&g_parth[rowoff + zs];
    float2 a0 = h2f(pa.x), a1 = h2f(pa.y), a2 = h2f(pa.z), a3 = h2f(pa.w);
    float2 c0 = h2f(pb.x), c1 = h2f(pb.y), c2 = h2f(pb.z), c3 = h2f(pb.w);
    float4 h0 = *(const float4*)&g_Hn[rowoff];
    float4 h1 = *(const float4*)&g_Hn[rowoff + 4];
    float4 bb0 = *(const float4*)&b2[lane * 8];
    float4 bb1 = *(const float4*)&b2[lane * 8 + 4];

    float v[8];
    v[0] = a0.x + c0.x + bb0.x + h0.x;
    v[1] = a0.y + c0.y + bb0.y + h0.y;
    v[2] = a1.x + c1.x + bb0.z + h0.z;
    v[3] = a1.y + c1.y + bb0.w + h0.w;
    v[4] = a2.x + c2.x + bb1.x + h1.x;
    v[5] = a2.y + c2.y + bb1.y + h1.y;
    v[6] = a3.x + c3.x + bb1.z + h1.z;
    v[7] = a3.y + c3.y + bb1.w + h1.w;

    float s = 0.f;
#pragma unroll
    for (int i = 0; i < 8; i++) s += v[i];
    float mu = warp_sum(s) * (1.f / CD);
    float s2 = 0.f;
#pragma unroll
    for (int i = 0; i < 8; i++) {
        v[i] -= mu;
        s2 += v[i] * v[i];
    }
    float rstd = rsqrtf(warp_sum(s2) * (1.f / CD) + 1e-5f);

    float4 g0 = *(const float4*)&gw[lane * 8];
    float4 g1v = *(const float4*)&gw[lane * 8 + 4];
    float4 w0 = *(const float4*)&bw[lane * 8];
    float4 w1 = *(const float4*)&bw[lane * 8 + 4];
    *(float4*)&out[rowoff] = make_float4(
        v[0] * rstd * g0.x + w0.x, v[1] * rstd * g0.y + w0.y,
        v[2] * rstd * g0.z + w0.z, v[3] * rstd * g0.w + w0.w);
    *(float4*)&out[rowoff + 4] = make_float4(
        v[4] * rstd * g1v.x + w1.x, v[5] * rstd * g1v.y + w1.y,
        v[6] * rstd * g1v.z + w1.z, v[7] * rstd * g1v.w + w1.w);
}

// ---------------------------------------------------------------------------
// kernel_launch
// ---------------------------------------------------------------------------
extern "C" void kernel_launch(void* const* d_in, const int* in_sizes, int n_in,
                              void* d_out, int out_size) {
    const float* x    = (const float*)d_in[0];
    const int*   mask = (const int*)  d_in[1];
    const float* W1   = (const float*)d_in[2];
    const float* b1   = (const float*)d_in[3];
    const float* W2   = (const float*)d_in[4];
    const float* b2   = (const float*)d_in[5];
    const float* g1   = (const float*)d_in[6];
    const float* be1  = (const float*)d_in[7];
    const float* g2   = (const float*)d_in[8];
    const float* be2  = (const float*)d_in[9];
    float* out = (float*)d_out;

    __half *pP, *pHnh, *pH1h, *pParth, *pxh, *pW1h, *pW2h;
    cudaGetSymbolAddress((void**)&pP,     g_P);
    cudaGetSymbolAddress((void**)&pParth, g_parth);
    cudaGetSymbolAddress((void**)&pHnh,   g_Hnh);
    cudaGetSymbolAddress((void**)&pH1h,   g_H1h);
    cudaGetSymbolAddress((void**)&pxh,    g_xh);
    cudaGetSymbolAddress((void**)&pW1h,   g_W1h);
    cudaGetSymbolAddress((void**)&pW2h,   g_W2h);

    const int DSMEM = 3 * 32768;
    cudaFuncSetAttribute(k_hgemm<64, 2>, cudaFuncAttributeMaxDynamicSharedMemorySize, DSMEM);
    cudaFuncSetAttribute(k_hgemm<35, 1>, cudaFuncAttributeMaxDynamicSharedMemorySize, DSMEM);

    // 1) token mean (half) + zero denominators
    k_mean<<<(CL * CDK + 255) / 256, 256>>>(x);
    // 2) tensor-core scores + fused masked denominators
    k_scores_mma<<<dim3(CL / 128, CL / 128), 256>>>(mask);
    // 3) merged half conversions (xh masked, W1h, W2h)
    k_convert<<<1280, 256>>>(x, mask, W1, W2);

    // 4) GEMM1 split-K2: parth[b*2+s] = P[:, ks] @ xh_b[ks, :]  (half partials)
    k_hgemm<64, 2><<<dim3(CD / 128, CL / 128, CB * 2), 256, DSMEM>>>(
        pP, pxh, nullptr, nullptr, pParth,
        CD, CL, (size_t)CL * CD, (size_t)CL * CD);

    // 5) reduce + /den + residual(x) + LN1 -> Hn, Hnh
    k_red_ln1<<<CB * CL / 8, 256>>>(x, g1, be1);

    // 6) H1h = half(relu(Hn @ W1 + b1))   OPT = 1|2|32
    k_hgemm<35, 1><<<dim3(CF / 128, (CB * CL) / 128, 1), 256, DSMEM>>>(
        pHnh, pW1h, b1, nullptr, pH1h,
        CF, CD, 0, 0);

    // 7) GEMM3 split-K2: parth[s] = H1h[:, ks] @ W2h[ks, :]  (half partials)
    k_hgemm<64, 2><<<dim3(CD / 128, (CB * CL) / 128, 2), 256, DSMEM>>>(
        pH1h, pW2h, nullptr, nullptr, pParth,
        CD, CF, 0, (size_t)CB * CL * CD);

    // 8) reduce + bias + residual(Hn) + LN2 -> out
    k_red_ln2<<<CB * CL / 8, 256>>>(b2, g2, be2, out);
}